// round 2
// baseline (speedup 1.0000x reference)
#include <cuda_runtime.h>

#define N_QUBITS 15
#define N_LAYERS 4
#define BATCHN   64
#define NSTATE   (1 << N_QUBITS)   // 32768
#define NTHREADS 512

// 16 MB L2-resident state scratch: [batch][32768] complex64 as float2.
__device__ float2 g_state[BATCHN * NSTATE];

__device__ __forceinline__ void crot(float2& a0, float2& a1,
                                     float2 u0, float2 u1, float2 u2, float2 u3) {
  float2 r0, r1;
  r0.x = u0.x * a0.x - u0.y * a0.y + u1.x * a1.x - u1.y * a1.y;
  r0.y = u0.x * a0.y + u0.y * a0.x + u1.x * a1.y + u1.y * a1.x;
  r1.x = u2.x * a0.x - u2.y * a0.y + u3.x * a1.x - u3.y * a1.y;
  r1.y = u2.x * a0.y + u2.y * a0.x + u3.x * a1.y + u3.y * a1.x;
  a0 = r0; a1 = r1;
}

// Rotation gate on register-local bit BIT of a 32-amp subcube.
template<int BIT>
__device__ __forceinline__ void rotg(float2* a, const float2* su) {
  float2 u0 = su[0], u1 = su[1], u2 = su[2], u3 = su[3];
#pragma unroll
  for (int j = 0; j < 32; j++) {
    if (((j >> BIT) & 1) == 0) {
      crot(a[j], a[j | (1 << BIT)], u0, u1, u2, u3);
    }
  }
}

// CNOT with both control (BC) and target (BT) in local bits: pure register permutation.
template<int BC, int BT>
__device__ __forceinline__ void cnotl(float2* a) {
#pragma unroll
  for (int j = 0; j < 32; j++) {
    if (((j >> BC) & 1) == 1 && ((j >> BT) & 1) == 0) {
      int k = j | (1 << BT);
      float2 t = a[j]; a[j] = a[k]; a[k] = t;
    }
  }
}

// X on local bit BT, conditioned on a runtime (thread-uniform-per-subcube) control bit.
template<int BT>
__device__ __forceinline__ void xcond(float2* a, bool c) {
#pragma unroll
  for (int j = 0; j < 32; j++) {
    if (((j >> BT) & 1) == 0) {
      int k = j | (1 << BT);
      float2 t0 = a[j], t1 = a[k];
      a[j] = c ? t1 : t0;
      a[k] = c ? t0 : t1;
    }
  }
}

// Amp index convention (row-major flatten of [2]*15): qubit q <-> bit (14 - q).
// Class = top 2 bits (qubits 0,1).
__global__ void __launch_bounds__(NTHREADS, 1)
qdarts_kernel(const float* __restrict__ x, const float* __restrict__ Pm,
              const float* __restrict__ Qm, const float* __restrict__ rotp,
              const float* __restrict__ gum, float* __restrict__ out)
{
  __shared__ float2 sU[N_LAYERS * N_QUBITS * 4];  // selected 2x2 gates
  __shared__ float  sw[N_QUBITS][2];              // encoding cos/sin per qubit
  __shared__ float  sred[4];

  const int tid = threadIdx.x;
  const int b = blockIdx.x;

  // ---- Gate selection: argmax(P@Q + gumbel); build RX/RY/RZ(theta). ----
  if (tid < N_LAYERS * N_QUBITS) {
    const int idx = tid;
    float best = -1e30f; int gb = 0;
#pragma unroll
    for (int g = 0; g < 3; g++) {
      float logit = 0.f;
#pragma unroll
      for (int k = 0; k < 4; k++)
        logit += Pm[idx * 4 + k] * Qm[(idx * 4 + k) * 3 + g];
      float v = logit + gum[idx * 3 + g];
      if (v > best) { best = v; gb = g; }
    }
    float th = rotp[idx];
    float s, c;
    sincosf(0.5f * th, &s, &c);
    float2 u0, u1, u2, u3;
    if (gb == 0) {        // RX
      u0 = make_float2(c, 0.f);  u1 = make_float2(0.f, -s);
      u2 = make_float2(0.f, -s); u3 = make_float2(c, 0.f);
    } else if (gb == 1) { // RY
      u0 = make_float2(c, 0.f);  u1 = make_float2(-s, 0.f);
      u2 = make_float2(s, 0.f);  u3 = make_float2(c, 0.f);
    } else {              // RZ
      u0 = make_float2(c, -s);   u1 = make_float2(0.f, 0.f);
      u2 = make_float2(0.f, 0.f); u3 = make_float2(c, s);
    }
    sU[idx * 4 + 0] = u0; sU[idx * 4 + 1] = u1;
    sU[idx * 4 + 2] = u2; sU[idx * 4 + 3] = u3;
  }
  if (tid < N_QUBITS) {
    float xv = x[b * N_QUBITS + tid];
    float s, c;
    sincosf(0.5f * xv, &s, &c);
    sw[tid][0] = c; sw[tid][1] = s;
  }
  if (tid < 4) sred[tid] = 0.f;
  __syncthreads();

  float2* S = g_state + b * NSTATE;

#pragma unroll 1
  for (int l = 0; l < N_LAYERS; l++) {
    const float2* UL = &sU[l * N_QUBITS * 4];

    // ---- Pass A: local qubits 0..4 (amp bits 14..10). amp = (j<<10)|g ----
#pragma unroll 1
    for (int it = 0; it < 2; it++) {
      const int g = tid + it * NTHREADS;  // amp bits 9..0
      float2 a[32];
      if (l == 0) {
        // Analytic post-encoding product state (all real).
        float pref = 1.f;
#pragma unroll
        for (int q = 5; q < 15; q++) pref *= sw[q][(g >> (14 - q)) & 1];
#pragma unroll
        for (int j = 0; j < 32; j++) {
          float v = pref;
#pragma unroll
          for (int q = 0; q < 5; q++) v *= sw[q][(j >> (4 - q)) & 1];
          a[j] = make_float2(v, 0.f);
        }
      } else {
#pragma unroll
        for (int j = 0; j < 32; j++) a[j] = S[(j << 10) | g];
        xcond<4>(a, (g & 1) != 0);  // deferred CNOT(14,0) of layer l-1
      }
      rotg<4>(a, UL + 0 * 4);  // R_q0
      rotg<3>(a, UL + 1 * 4);  // R_q1
      rotg<2>(a, UL + 2 * 4);  // R_q2
      rotg<1>(a, UL + 3 * 4);  // R_q3
      rotg<0>(a, UL + 4 * 4);  // R_q4
      cnotl<4, 3>(a);  // CNOT(0,1)
      cnotl<3, 2>(a);  // CNOT(1,2)
      cnotl<2, 1>(a);  // CNOT(2,3)
      cnotl<1, 0>(a);  // CNOT(3,4)
#pragma unroll
      for (int j = 0; j < 32; j++) S[(j << 10) | g] = a[j];
    }
    __syncthreads();

    // ---- Pass B: local qubits 5..9 (amp bits 9..5). amp = base|(j<<5) ----
#pragma unroll 1
    for (int it = 0; it < 2; it++) {
      const int g = tid + it * NTHREADS;
      const int base = ((g >> 5) << 10) | (g & 31);
      float2 a[32];
#pragma unroll
      for (int j = 0; j < 32; j++) a[j] = S[base | (j << 5)];
      rotg<4>(a, UL + 5 * 4);  // R_q5
      rotg<3>(a, UL + 6 * 4);  // R_q6
      rotg<2>(a, UL + 7 * 4);  // R_q7
      rotg<1>(a, UL + 8 * 4);  // R_q8
      rotg<0>(a, UL + 9 * 4);  // R_q9
      xcond<4>(a, (g & 32) != 0);  // CNOT(4,5): control amp bit10 = g bit5
      cnotl<4, 3>(a);  // CNOT(5,6)
      cnotl<3, 2>(a);  // CNOT(6,7)
      cnotl<2, 1>(a);  // CNOT(7,8)
      cnotl<1, 0>(a);  // CNOT(8,9)
#pragma unroll
      for (int j = 0; j < 32; j++) S[base | (j << 5)] = a[j];
    }
    __syncthreads();

    // ---- Pass C: local qubits 10..14 (amp bits 4..0). amp = (g<<5)|j ----
#pragma unroll 1
    for (int it = 0; it < 2; it++) {
      const int g = tid + it * NTHREADS;
      const int base = g << 5;
      float2 a[32];
#pragma unroll
      for (int j = 0; j < 32; j++) a[j] = S[base | j];
      rotg<4>(a, UL + 10 * 4);  // R_q10
      rotg<3>(a, UL + 11 * 4);  // R_q11
      rotg<2>(a, UL + 12 * 4);  // R_q12
      rotg<1>(a, UL + 13 * 4);  // R_q13
      rotg<0>(a, UL + 14 * 4);  // R_q14
      xcond<4>(a, (g & 1) != 0);  // CNOT(9,10): control amp bit5 = g bit0
      cnotl<4, 3>(a);  // CNOT(10,11)
      cnotl<3, 2>(a);  // CNOT(11,12)
      cnotl<2, 1>(a);  // CNOT(12,13)
      cnotl<1, 0>(a);  // CNOT(13,14)
#pragma unroll
      for (int j = 0; j < 32; j++) S[base | j] = a[j];
    }
    __syncthreads();
  }

  // ---- Final: layer-3 CNOT(14,0) folded into class remap + |amp|^2 reduce ----
  // Layout of pass A: j bits 4..3 = amp bits 14..13 = class bits.
  // CNOT(14,0) flips amp bit14 (class MSB) when g bit0 set.
  float ps0 = 0.f, ps1 = 0.f, ps2 = 0.f, ps3 = 0.f;
#pragma unroll 1
  for (int it = 0; it < 2; it++) {
    const int g = tid + it * NTHREADS;
    float t0 = 0.f, t1 = 0.f, t2 = 0.f, t3 = 0.f;
#pragma unroll
    for (int j = 0; j < 32; j++) {
      float2 v = S[(j << 10) | g];
      float p = v.x * v.x + v.y * v.y;
      if ((j >> 3) == 0) t0 += p;
      else if ((j >> 3) == 1) t1 += p;
      else if ((j >> 3) == 2) t2 += p;
      else t3 += p;
    }
    if (g & 1) { ps0 += t2; ps1 += t3; ps2 += t0; ps3 += t1; }
    else       { ps0 += t0; ps1 += t1; ps2 += t2; ps3 += t3; }
  }
#pragma unroll
  for (int o = 16; o > 0; o >>= 1) {
    ps0 += __shfl_xor_sync(0xffffffffu, ps0, o);
    ps1 += __shfl_xor_sync(0xffffffffu, ps1, o);
    ps2 += __shfl_xor_sync(0xffffffffu, ps2, o);
    ps3 += __shfl_xor_sync(0xffffffffu, ps3, o);
  }
  if ((tid & 31) == 0) {
    atomicAdd(&sred[0], ps0);
    atomicAdd(&sred[1], ps1);
    atomicAdd(&sred[2], ps2);
    atomicAdd(&sred[3], ps3);
  }
  __syncthreads();
  if (tid < 4) out[b * 4 + tid] = sred[tid];
}

extern "C" void kernel_launch(void* const* d_in, const int* in_sizes, int n_in,
                              void* d_out, int out_size) {
  const float* x    = (const float*)d_in[0];
  const float* P    = (const float*)d_in[1];
  const float* Q    = (const float*)d_in[2];
  const float* rotp = (const float*)d_in[3];
  const float* gum  = (const float*)d_in[4];
  qdarts_kernel<<<BATCHN, NTHREADS>>>(x, P, Q, rotp, gum, (float*)d_out);
}

// round 3
// speedup vs baseline: 2.2918x; 2.2918x over previous
#include <cuda_runtime.h>
#include <cooperative_groups.h>

namespace cg = cooperative_groups;

#define N_QUBITS 15
#define N_LAYERS 4
#define BATCHN   64
#define NSTATE   (1 << N_QUBITS)   // 32768
#define NTHREADS 512

// 16 MB L2-resident state scratch: [batch][32768] complex64 as float2.
__device__ float2 g_state[BATCHN * NSTATE];

__device__ __forceinline__ void crot(float2& a0, float2& a1,
                                     float2 u0, float2 u1, float2 u2, float2 u3) {
  float2 r0, r1;
  r0.x = u0.x * a0.x - u0.y * a0.y + u1.x * a1.x - u1.y * a1.y;
  r0.y = u0.x * a0.y + u0.y * a0.x + u1.x * a1.y + u1.y * a1.x;
  r1.x = u2.x * a0.x - u2.y * a0.y + u3.x * a1.x - u3.y * a1.y;
  r1.y = u2.x * a0.y + u2.y * a0.x + u3.x * a1.y + u3.y * a1.x;
  a0 = r0; a1 = r1;
}

template<int BIT>
__device__ __forceinline__ void rotg(float2* a, const float2* su) {
  float2 u0 = su[0], u1 = su[1], u2 = su[2], u3 = su[3];
#pragma unroll
  for (int j = 0; j < 32; j++) {
    if (((j >> BIT) & 1) == 0) {
      crot(a[j], a[j | (1 << BIT)], u0, u1, u2, u3);
    }
  }
}

template<int BC, int BT>
__device__ __forceinline__ void cnotl(float2* a) {
#pragma unroll
  for (int j = 0; j < 32; j++) {
    if (((j >> BC) & 1) == 1 && ((j >> BT) & 1) == 0) {
      int k = j | (1 << BT);
      float2 t = a[j]; a[j] = a[k]; a[k] = t;
    }
  }
}

template<int BT>
__device__ __forceinline__ void xcond(float2* a, bool c) {
#pragma unroll
  for (int j = 0; j < 32; j++) {
    if (((j >> BT) & 1) == 0) {
      int k = j | (1 << BT);
      float2 t0 = a[j], t1 = a[k];
      a[j] = c ? t1 : t0;
      a[k] = c ? t0 : t1;
    }
  }
}

// Amp index convention: qubit q <-> bit (14 - q). Class = amp bits 14..13.
__global__ void __launch_bounds__(NTHREADS, 1) __cluster_dims__(2, 1, 1)
qdarts_kernel(const float* __restrict__ x, const float* __restrict__ Pm,
              const float* __restrict__ Qm, const float* __restrict__ rotp,
              const float* __restrict__ gum, float* __restrict__ out)
{
  __shared__ float2 sU[N_LAYERS * N_QUBITS * 4];
  __shared__ float  sw[N_QUBITS][2];
  __shared__ float  sred[4];

  cg::cluster_group cluster = cg::this_cluster();
  const int tid  = threadIdx.x;
  const int b    = blockIdx.x >> 1;
  const int half = blockIdx.x & 1;       // == cluster.block_rank()
  const int g    = (half << 9) | tid;    // this CTA's subcube id, 0..1023

  // ---- Gate selection: argmax(P@Q + gumbel); build RX/RY/RZ(theta). ----
  if (tid < N_LAYERS * N_QUBITS) {
    const int idx = tid;
    float best = -1e30f; int gb = 0;
#pragma unroll
    for (int gg = 0; gg < 3; gg++) {
      float logit = 0.f;
#pragma unroll
      for (int k = 0; k < 4; k++)
        logit += Pm[idx * 4 + k] * Qm[(idx * 4 + k) * 3 + gg];
      float v = logit + gum[idx * 3 + gg];
      if (v > best) { best = v; gb = gg; }
    }
    float th = rotp[idx];
    float s, c;
    sincosf(0.5f * th, &s, &c);
    float2 u0, u1, u2, u3;
    if (gb == 0) {        // RX
      u0 = make_float2(c, 0.f);  u1 = make_float2(0.f, -s);
      u2 = make_float2(0.f, -s); u3 = make_float2(c, 0.f);
    } else if (gb == 1) { // RY
      u0 = make_float2(c, 0.f);  u1 = make_float2(-s, 0.f);
      u2 = make_float2(s, 0.f);  u3 = make_float2(c, 0.f);
    } else {              // RZ
      u0 = make_float2(c, -s);    u1 = make_float2(0.f, 0.f);
      u2 = make_float2(0.f, 0.f); u3 = make_float2(c, s);
    }
    sU[idx * 4 + 0] = u0; sU[idx * 4 + 1] = u1;
    sU[idx * 4 + 2] = u2; sU[idx * 4 + 3] = u3;
  }
  if (tid < N_QUBITS) {
    float xv = x[b * N_QUBITS + tid];
    float s, c;
    sincosf(0.5f * xv, &s, &c);
    sw[tid][0] = c; sw[tid][1] = s;
  }
  if (tid < 4) sred[tid] = 0.f;
  __syncthreads();

  float2* S = g_state + b * NSTATE;
  float ps0 = 0.f, ps1 = 0.f, ps2 = 0.f, ps3 = 0.f;

#pragma unroll 1
  for (int l = 0; l < N_LAYERS; l++) {
    const float2* UL = &sU[l * N_QUBITS * 4];

    // ---- Pass A: local amp bits 14..10 (qubits 0..4). amp = (j<<10)|g ----
    {
      float2 a[32];
      if (l == 0) {
        float pref = 1.f;
#pragma unroll
        for (int q = 5; q < 15; q++) pref *= sw[q][(g >> (14 - q)) & 1];
#pragma unroll
        for (int j = 0; j < 32; j++) {
          float v = pref;
#pragma unroll
          for (int q = 0; q < 5; q++) v *= sw[q][(j >> (4 - q)) & 1];
          a[j] = make_float2(v, 0.f);
        }
      } else {
#pragma unroll
        for (int j = 0; j < 32; j++) a[j] = S[(j << 10) | g];
        xcond<4>(a, (g & 1) != 0);  // deferred CNOT(14,0) of layer l-1
      }
      rotg<4>(a, UL + 0 * 4);
      rotg<3>(a, UL + 1 * 4);
      rotg<2>(a, UL + 2 * 4);
      rotg<1>(a, UL + 3 * 4);
      rotg<0>(a, UL + 4 * 4);
      cnotl<4, 3>(a);
      cnotl<3, 2>(a);
      cnotl<2, 1>(a);
      cnotl<1, 0>(a);
#pragma unroll
      for (int j = 0; j < 32; j++) S[(j << 10) | g] = a[j];
    }
    cluster.sync();

    // ---- Pass B: local amp bits 9..5 (qubits 5..9). amp = base|(j<<5) ----
    {
      const int base = ((g >> 5) << 10) | (g & 31);
      float2 a[32];
#pragma unroll
      for (int j = 0; j < 32; j++) a[j] = S[base | (j << 5)];
      rotg<4>(a, UL + 5 * 4);
      rotg<3>(a, UL + 6 * 4);
      rotg<2>(a, UL + 7 * 4);
      rotg<1>(a, UL + 8 * 4);
      rotg<0>(a, UL + 9 * 4);
      xcond<4>(a, (g & 32) != 0);  // CNOT(4,5)
      cnotl<4, 3>(a);
      cnotl<3, 2>(a);
      cnotl<2, 1>(a);
      cnotl<1, 0>(a);
#pragma unroll
      for (int j = 0; j < 32; j++) S[base | (j << 5)] = a[j];
    }
    cluster.sync();

    // ---- Pass C: local amp bits 4..0 (qubits 10..14). amp = (g<<5)|j ----
    {
      const int base = g << 5;
      float2 a[32];
      const float4* pv = (const float4*)(S + base);
#pragma unroll
      for (int j2 = 0; j2 < 16; j2++) {
        float4 v = pv[j2];
        a[2 * j2]     = make_float2(v.x, v.y);
        a[2 * j2 + 1] = make_float2(v.z, v.w);
      }
      rotg<4>(a, UL + 10 * 4);
      rotg<3>(a, UL + 11 * 4);
      rotg<2>(a, UL + 12 * 4);
      rotg<1>(a, UL + 13 * 4);
      rotg<0>(a, UL + 14 * 4);
      xcond<4>(a, (g & 1) != 0);  // CNOT(9,10)
      cnotl<4, 3>(a);
      cnotl<3, 2>(a);
      cnotl<2, 1>(a);
      cnotl<1, 0>(a);

      if (l < N_LAYERS - 1) {
        float4* pw = (float4*)(S + base);
#pragma unroll
        for (int j2 = 0; j2 < 16; j2++) {
          pw[j2] = make_float4(a[2 * j2].x, a[2 * j2].y,
                               a[2 * j2 + 1].x, a[2 * j2 + 1].y);
        }
      } else {
        // Last layer: fold CNOT(14,0) + |amp|^2 class reduction here.
        // amp bit0 = j&1 (control), class bits = amp 14..13 = g bits 9..8.
        float pe = 0.f, po = 0.f;
#pragma unroll
        for (int j = 0; j < 32; j++) {
          float p = a[j].x * a[j].x + a[j].y * a[j].y;
          if (j & 1) po += p; else pe += p;
        }
        const int c = (g >> 8) & 3;   // pe -> class c, po -> class c^2
        if      (c == 0) { ps0 = pe; ps2 = po; }
        else if (c == 1) { ps1 = pe; ps3 = po; }
        else if (c == 2) { ps2 = pe; ps0 = po; }
        else             { ps3 = pe; ps1 = po; }
      }
    }
    if (l < N_LAYERS - 1) cluster.sync();
  }

  // ---- Reduce class sums: warp -> CTA shared -> cross-CTA (DSMEM) ----
#pragma unroll
  for (int o = 16; o > 0; o >>= 1) {
    ps0 += __shfl_xor_sync(0xffffffffu, ps0, o);
    ps1 += __shfl_xor_sync(0xffffffffu, ps1, o);
    ps2 += __shfl_xor_sync(0xffffffffu, ps2, o);
    ps3 += __shfl_xor_sync(0xffffffffu, ps3, o);
  }
  if ((tid & 31) == 0) {
    atomicAdd(&sred[0], ps0);
    atomicAdd(&sred[1], ps1);
    atomicAdd(&sred[2], ps2);
    atomicAdd(&sred[3], ps3);
  }
  __syncthreads();

  if (half == 1 && tid < 4) {
    float* dst = cluster.map_shared_rank(sred, 0);
    atomicAdd(dst + tid, sred[tid]);
  }
  cluster.sync();
  if (half == 0 && tid < 4) out[b * 4 + tid] = sred[tid];
}

extern "C" void kernel_launch(void* const* d_in, const int* in_sizes, int n_in,
                              void* d_out, int out_size) {
  const float* x    = (const float*)d_in[0];
  const float* P    = (const float*)d_in[1];
  const float* Q    = (const float*)d_in[2];
  const float* rotp = (const float*)d_in[3];
  const float* gum  = (const float*)d_in[4];
  qdarts_kernel<<<BATCHN * 2, NTHREADS>>>(x, P, Q, rotp, gum, (float*)d_out);
}